// round 2
// baseline (speedup 1.0000x reference)
#include <cuda_runtime.h>
#include <math.h>

// Problem constants
#define DIMC   64
#define HEADS  8
#define WINN   4
#define LTOK   36     // 4 windows * 9 taps
#define WSS    128    // window spatial size
#define BATCH  8

// Dynamic conv weights, layout [w][ic][p][oc]  (oc contiguous)
__device__ float g_W[WINN * DIMC * 9 * DIMC];

// ---------------------------------------------------------------------------
// Stage 1: build dynamic conv kernels.
// One block per attention-batch index b (= conv output channel), 64 blocks.
// kern0[l][i] = conv_w[w, b, i, p]   (l = w*9+p)
// qkv -> 8-head attention over 36 tokens -> out proj -> SE gate -> g_W
// ---------------------------------------------------------------------------
__global__ __launch_bounds__(288) void stage1_kernel(
    const float* __restrict__ conv_w, const float* __restrict__ w_qkv,
    const float* __restrict__ b_qkv,  const float* __restrict__ w_out,
    const float* __restrict__ b_out,  const float* __restrict__ se_w1,
    const float* __restrict__ se_b1,  const float* __restrict__ se_w2,
    const float* __restrict__ se_b2)
{
    const int b   = blockIdx.x;     // output channel 0..63
    const int tid = threadIdx.x;

    __shared__ float sA[LTOK * 64];     // kern0, later attn-out (out2)
    __shared__ float sQ[LTOK * 192];    // qkv, later kern2 (first 2304 floats)
    __shared__ float pooled[4][64];
    __shared__ float hr[4][4];

    // --- load kern0 ---
    for (int t = tid; t < LTOK * 64; t += 288) {
        int l = t >> 6, i = t & 63;
        int w = l / 9, p = l - w * 9;
        sA[t] = conv_w[(((w * 64 + b) * 64 + i) * 9) + p];
    }
    __syncthreads();

    // --- qkv projection: qkv[l][j] = kern0[l] . w_qkv[j] + b_qkv[j] ---
    for (int t = tid; t < LTOK * 192; t += 288) {
        int l = t / 192, j = t - l * 192;
        float acc = b_qkv[j];
        const float* wr = w_qkv + j * 64;
        const float* kr = sA + l * 64;
        #pragma unroll
        for (int i = 0; i < 64; i++) acc = fmaf(kr[i], wr[i], acc);
        sQ[t] = acc;
    }
    __syncthreads();

    // --- attention: thread = (head h, query l); 8*36 = 288 threads ---
    {
        int h = tid / 36, l = tid - h * 36;
        const int qo = h * 8;           // q offset within 192
        float sc[36];
        float mx = -1e30f;
        const float scale = 0.35355339059327373f;   // 8^-0.5
        for (int m = 0; m < 36; m++) {
            float s = 0.f;
            #pragma unroll
            for (int d = 0; d < 8; d++)
                s = fmaf(sQ[l * 192 + qo + d], sQ[m * 192 + 64 + qo + d], s);
            s *= scale;
            sc[m] = s;
            mx = fmaxf(mx, s);
        }
        float sum = 0.f;
        for (int m = 0; m < 36; m++) { float e = expf(sc[m] - mx); sc[m] = e; sum += e; }
        float inv = 1.f / sum;
        float o[8];
        #pragma unroll
        for (int d = 0; d < 8; d++) o[d] = 0.f;
        for (int m = 0; m < 36; m++) {
            float a = sc[m];
            #pragma unroll
            for (int d = 0; d < 8; d++)
                o[d] = fmaf(a, sQ[m * 192 + 128 + qo + d], o[d]);
        }
        // write out2 into sA (kern0 no longer needed; qkv reads already done)
        #pragma unroll
        for (int d = 0; d < 8; d++) sA[l * 64 + qo + d] = o[d] * inv;
    }
    __syncthreads();

    // --- output projection: kern2[l][j] = out2[l] . w_out[j] + b_out[j] -> sQ ---
    for (int t = tid; t < LTOK * 64; t += 288) {
        int l = t >> 6, j = t & 63;
        float acc = b_out[j];
        const float* wr = w_out + j * 64;
        const float* orow = sA + l * 64;
        #pragma unroll
        for (int i = 0; i < 64; i++) acc = fmaf(orow[i], wr[i], acc);
        sQ[t] = acc;                 // kern2, row stride 64
    }
    __syncthreads();

    // --- SE: pooled over the 9 taps of each window ---
    if (tid < 256) {
        int w = tid >> 6, i = tid & 63;
        float s = 0.f;
        #pragma unroll
        for (int p = 0; p < 9; p++) s += sQ[(w * 9 + p) * 64 + i];
        pooled[w][i] = s * (1.f / 9.f);
    }
    __syncthreads();
    if (tid < 16) {
        int w = tid >> 2, r = tid & 3;
        float acc = se_b1[w * 4 + r];
        #pragma unroll
        for (int i = 0; i < 64; i++)
            acc = fmaf(pooled[w][i], se_w1[(w * 4 + r) * 64 + i], acc);
        hr[w][r] = fmaxf(acc, 0.f);
    }
    __syncthreads();
    if (tid < 256) {
        int w = tid >> 6, i = tid & 63;
        float acc = se_b2[w * 64 + i];
        #pragma unroll
        for (int r = 0; r < 4; r++)
            acc = fmaf(hr[w][r], se_w2[(w * 64 + i) * 4 + r], acc);
        float g = 1.f / (1.f + expf(-acc));
        // g_W[w][ic=i][p][oc=b] = kern2[w*9+p][i] * gate
        #pragma unroll
        for (int p = 0; p < 9; p++)
            g_W[((w * 64 + i) * 9 + p) * 64 + b] = sQ[(w * 9 + p) * 64 + i] * g;
    }
}

// ---------------------------------------------------------------------------
// Stage 2: per-window dynamic 3x3 conv (zero pad at window edges) fused with
// channel-last LayerNorm + residual.
// Block = one 16x16 pixel tile of one (batch, window) image, all 64 out chans.
// Thread register tile: 8 oc x 8 px. K loop in 4 chunks of 16 input channels.
// Shared: input halo 16x18x18, weight chunk 16x9x64, LN reduction 2x8x256.
// ---------------------------------------------------------------------------
#define ISH_SZ   (16 * 324)          // 16 ic * 18*18
#define WSH_SZ   (16 * 9 * 64)
#define RED_SZ   (2 * 8 * 256)
#define SMEM2_BYTES ((ISH_SZ + WSH_SZ + RED_SZ) * 4)

__global__ __launch_bounds__(256, 2) void stage2_kernel(
    const float* __restrict__ x, const float* __restrict__ ln_w,
    const float* __restrict__ ln_b, float* __restrict__ out)
{
    extern __shared__ float sm[];
    float* Ish  = sm;                       // [16][324]
    float* Wsh  = sm + ISH_SZ;              // [16][9][64]
    float* Rsum = Wsh + WSH_SZ;             // [8][256]
    float* Rsq  = Rsum + 8 * 256;           // [8][256]

    const int blk  = blockIdx.x;
    const int tile = blk & 63;
    const int img  = blk >> 6;
    const int w    = img & 3, b = img >> 2;
    const int ty0  = (tile >> 3) << 4;
    const int tx0  = (tile & 7) << 4;
    const int wh   = w >> 1, ww = w & 1;
    const int gy0  = wh * 128 + ty0, gx0 = ww * 128 + tx0;

    const int tid = threadIdx.x;
    const int tp  = tid & 31;       // pixel group (8 px strided by 32)
    const int to  = tid >> 5;       // oc group
    const int oc0 = to << 3;

    int ioff[8];
    #pragma unroll
    for (int j = 0; j < 8; j++) {
        int m = tp + 32 * j;
        ioff[j] = (m >> 4) * 18 + (m & 15);
    }

    float acc[8][8];
    #pragma unroll
    for (int o = 0; o < 8; o++)
        #pragma unroll
        for (int j = 0; j < 8; j++) acc[o][j] = 0.f;

    const float* xb = x + (size_t)b * (64 * 256 * 256);
    const float* Wg = g_W + w * (64 * 9 * 64);

    for (int ic0 = 0; ic0 < 64; ic0 += 16) {
        // stage input halo tile (zero pad at window boundary)
        for (int t = tid; t < ISH_SZ; t += 256) {
            int icl = t / 324;
            int rem = t - icl * 324;
            int yy = rem / 18, xx = rem - yy * 18;
            int ly = ty0 + yy - 1, lx = tx0 + xx - 1;
            float v = 0.f;
            if (ly >= 0 && ly < WSS && lx >= 0 && lx < WSS)
                v = xb[(size_t)(ic0 + icl) * 65536 + (wh * 128 + ly) * 256 + (ww * 128 + lx)];
            Ish[t] = v;
        }
        // stage weight chunk (contiguous copy)
        {
            const float* wsrc = Wg + ic0 * 576;
            for (int t = tid; t < WSH_SZ; t += 256) Wsh[t] = wsrc[t];
        }
        __syncthreads();

        #pragma unroll 1
        for (int icl = 0; icl < 16; icl++) {
            const float* Ibase = Ish + icl * 324;
            const float* Wbase = Wsh + icl * 576 + oc0;
            #pragma unroll
            for (int p = 0; p < 9; p++) {
                const int koff = (p / 3) * 18 + (p % 3);
                float4 w0 = *(const float4*)(Wbase + p * 64);
                float4 w1 = *(const float4*)(Wbase + p * 64 + 4);
                float in[8];
                #pragma unroll
                for (int j = 0; j < 8; j++) in[j] = Ibase[ioff[j] + koff];
                #pragma unroll
                for (int j = 0; j < 8; j++) {
                    acc[0][j] = fmaf(w0.x, in[j], acc[0][j]);
                    acc[1][j] = fmaf(w0.y, in[j], acc[1][j]);
                    acc[2][j] = fmaf(w0.z, in[j], acc[2][j]);
                    acc[3][j] = fmaf(w0.w, in[j], acc[3][j]);
                    acc[4][j] = fmaf(w1.x, in[j], acc[4][j]);
                    acc[5][j] = fmaf(w1.y, in[j], acc[5][j]);
                    acc[6][j] = fmaf(w1.z, in[j], acc[6][j]);
                    acc[7][j] = fmaf(w1.w, in[j], acc[7][j]);
                }
            }
        }
        __syncthreads();
    }

    // ---- LayerNorm over channels (deterministic staged reduction) ----
    #pragma unroll
    for (int j = 0; j < 8; j++) {
        float s = 0.f, sq = 0.f;
        #pragma unroll
        for (int o = 0; o < 8; o++) { s += acc[o][j]; sq = fmaf(acc[o][j], acc[o][j], sq); }
        int px = tp + 32 * j;
        Rsum[to * 256 + px] = s;
        Rsq [to * 256 + px] = sq;
    }
    __syncthreads();
    float mu_, rstd_;
    {
        float s = 0.f, sq = 0.f;
        #pragma unroll
        for (int g = 0; g < 8; g++) { s += Rsum[g * 256 + tid]; sq += Rsq[g * 256 + tid]; }
        mu_ = s * (1.f / 64.f);
        float var = sq * (1.f / 64.f) - mu_ * mu_;
        rstd_ = rsqrtf(var + 1e-5f);
    }
    __syncthreads();
    Rsum[tid] = mu_;
    Rsq[tid]  = rstd_;
    __syncthreads();

    float lw[8], lb[8];
    #pragma unroll
    for (int o = 0; o < 8; o++) { lw[o] = ln_w[oc0 + o]; lb[o] = ln_b[oc0 + o]; }

    #pragma unroll
    for (int j = 0; j < 8; j++) {
        int m  = tp + 32 * j;
        int gy = gy0 + (m >> 4);
        int gx = gx0 + (m & 15);
        float mu = Rsum[m], rs = Rsq[m];
        #pragma unroll
        for (int o = 0; o < 8; o++) {
            size_t gi = ((size_t)(b * 64 + oc0 + o) * 256 + gy) * 256 + gx;
            out[gi] = x[gi] + (acc[o][j] - mu) * rs * lw[o] + lb[o];
        }
    }
}

// ---------------------------------------------------------------------------
extern "C" void kernel_launch(void* const* d_in, const int* in_sizes, int n_in,
                              void* d_out, int out_size)
{
    (void)in_sizes; (void)n_in; (void)out_size;
    const float* x      = (const float*)d_in[0];
    const float* conv_w = (const float*)d_in[1];
    const float* w_qkv  = (const float*)d_in[2];
    const float* b_qkv  = (const float*)d_in[3];
    const float* w_out  = (const float*)d_in[4];
    const float* b_out  = (const float*)d_in[5];
    const float* se_w1  = (const float*)d_in[6];
    const float* se_b1  = (const float*)d_in[7];
    const float* se_w2  = (const float*)d_in[8];
    const float* se_b2  = (const float*)d_in[9];
    const float* ln_w   = (const float*)d_in[10];
    const float* ln_b   = (const float*)d_in[11];
    float* out = (float*)d_out;

    cudaFuncSetAttribute(stage2_kernel,
                         cudaFuncAttributeMaxDynamicSharedMemorySize, SMEM2_BYTES);

    stage1_kernel<<<64, 288>>>(conv_w, w_qkv, b_qkv, w_out, b_out,
                               se_w1, se_b1, se_w2, se_b2);
    stage2_kernel<<<2048, 256, SMEM2_BYTES>>>(x, ln_w, ln_b, out);
}